// round 12
// baseline (speedup 1.0000x reference)
#include <cuda_runtime.h>
#include <cstdint>

#define N_NODES 1024
#define F_IN    32
#define HID     64
#define OUTF    32

typedef unsigned long long u64;

// Scratch
__device__ float g_A [N_NODES * HID];
__device__ float g_Bq[16 * N_NODES * 4];   // quad-packed: [hq][node][4 floats]
__device__ float g_W2T[HID * OUTF];        // W2^T [h][o]

// Constant copies (uniform broadcast operands -> constant port)
__constant__ float c_W2T[HID * OUTF];
__constant__ float c_b2 [OUTF];

// ---------------------------------------------------------------------------
// Prep: 128 blocks x 256 threads, 8 nodes/block. W1 staged in padded smem.
// Block 0 also writes the W2 transpose into g_W2T.
// ---------------------------------------------------------------------------
__global__ __launch_bounds__(256) void prep_kernel(const float* __restrict__ Emb,
                                                   const float* __restrict__ W1,
                                                   const float* __restrict__ W2) {
    __shared__ float sW1[HID * 65];
    __shared__ float sE[8 * F_IN];
    const int tid = threadIdx.x;
    const int i0  = blockIdx.x * 8;

    if (blockIdx.x == 0) {
        for (int idx = tid; idx < OUTF * HID; idx += 256) {
            int o = idx >> 6, h = idx & 63;
            g_W2T[h * OUTF + o] = W2[idx];
        }
    }

    {
        const float4* w4 = (const float4*)W1;
        for (int v = tid; v < HID * 2 * F_IN / 4; v += 256) {
            float4 w = __ldg(w4 + v);
            int r = v >> 4, c = (v & 15) * 4;
            float* dst = &sW1[r * 65 + c];
            dst[0] = w.x; dst[1] = w.y; dst[2] = w.z; dst[3] = w.w;
        }
    }
    if (tid < 64) {
        float4 e = __ldg((const float4*)(Emb + i0 * F_IN) + tid);
        float* dst = &sE[tid * 4];
        dst[0] = e.x; dst[1] = e.y; dst[2] = e.z; dst[3] = e.w;
    }
    __syncthreads();

    const int h = tid & 63;
    const int g = tid >> 6;
#pragma unroll
    for (int k = 0; k < 2; k++) {
        const int n = g * 2 + k;
        const float* e = &sE[n * F_IN];
        float a = 0.f, b = 0.f;
#pragma unroll
        for (int f = 0; f < F_IN; f++) {
            float ev = e[f];
            a = fmaf(ev, sW1[h * 65 + f], a);
            b = fmaf(ev, sW1[h * 65 + F_IN + f], b);
        }
        const int i = i0 + n;
        g_A[i * HID + h] = a;
        g_Bq[(h >> 2) * (N_NODES * 4) + i * 4 + (h & 3)] = b;
    }
}

// ---------------------------------------------------------------------------
__device__ __forceinline__ u64 pack2(float lo, float hi) {
    u64 r; asm("mov.b64 %0, {%1,%2};" : "=l"(r) : "f"(lo), "f"(hi)); return r;
}
__device__ __forceinline__ void unpack2(u64 v, float& lo, float& hi) {
    asm("mov.b64 {%0,%1}, %2;" : "=f"(lo), "=f"(hi) : "l"(v));
}
__device__ __forceinline__ void fma2(u64& acc, u64 a, u64 b) {
    asm("fma.rn.f32x2 %0, %1, %2, %0;" : "+l"(acc) : "l"(a), "l"(b));
}
__device__ __forceinline__ u64 fma2r(u64 a, u64 b, u64 c) {
    u64 d; asm("fma.rn.f32x2 %0, %1, %2, %3;" : "=l"(d) : "l"(a), "l"(b), "l"(c)); return d;
}
__device__ __forceinline__ u64 add2r(u64 a, u64 b) {
    u64 d; asm("add.rn.f32x2 %0, %1, %2;" : "=l"(d) : "l"(a), "l"(b)); return d;
}
__device__ __forceinline__ u64 mul2r(u64 a, u64 b) {
    u64 d; asm("mul.rn.f32x2 %0, %1, %2;" : "=l"(d) : "l"(a), "l"(b)); return d;
}
__device__ __forceinline__ float tanhf_a(float x) {
    float t; asm("tanh.approx.f32 %0, %1;" : "=f"(t) : "f"(x)); return t;
}
// Packed swish from packed half-inputs: h = hx + hx*tanh(hx), both lanes.
// MUFU tanh is scalar; the multiply-add is packed.
__device__ __forceinline__ u64 swish2_from_half(u64 hx) {
    float x0, x1;
    unpack2(hx, x0, x1);
    u64 tp = pack2(tanhf_a(x0), tanhf_a(x1));
    return fma2r(hx, tp, hx);
}

// ---------------------------------------------------------------------------
// Dynamic smem layout (bytes)
// ---------------------------------------------------------------------------
#define SM_BQ   0        // 16 hq x 64 j x 16B = 16384
#define SM_AQ   16384    // 8 warps x 16 hq x 16B = 2048
#define SM_B1Q  18432    // 16 x 16B = 256 (b1/2, quad-packed)
#define SM_OUT  18688    // 8 warps x 32 lanes x 36 floats = 36864
#define SMEM_TOTAL 55552

// ---------------------------------------------------------------------------
// Main: grid (N/64, N/8), block 256 = 8 warps. Lane owns pairs (i, j0+lane)
// and (i, j0+32+lane). Phase A fully packed (0.5 folded into w and b1, packed
// post-tanh fma); B tile quad-packed for LDS.128; W2^T from constant port;
// b2-preseeded accs; STS.128 + LDS.64/STG.64 transpose epilogue.
// ---------------------------------------------------------------------------
__global__ __launch_bounds__(256, 2) void phi_e_kernel(
    const float* __restrict__ Edges,
    const float* __restrict__ Coords,
    const float* __restrict__ b1,
    float* __restrict__ out)
{
    extern __shared__ __align__(16) char smem[];
    ulonglong2 (*sBq)[64] = (ulonglong2(*)[64])(smem + SM_BQ);
    ulonglong2 (*sAq)[16] = (ulonglong2(*)[16])(smem + SM_AQ);
    ulonglong2* sB1q      = (ulonglong2*)(smem + SM_B1Q);
    float*      sOutBase  = (float*)(smem + SM_OUT);

    const int tid  = threadIdx.x;
    const int warp = tid >> 5;
    const int lane = tid & 31;
    const int i0 = blockIdx.y * 8;
    const int j0 = blockIdx.x * 64;
    const int i  = i0 + warp;

    {
        const ulonglong2* src = (const ulonglong2*)g_Bq;
        for (int e = tid; e < 16 * 64; e += 256) {
            int hq = e >> 6, jj = e & 63;
            sBq[hq][jj] = src[hq * N_NODES + j0 + jj];
        }
    }
    if (lane < 16)
        ((float4*)&sAq[warp][0])[lane] = ((const float4*)(g_A + i * HID))[lane];
    if (tid < 16) {
        float4 v = ((const float4*)b1)[tid];
        v.x *= 0.5f; v.y *= 0.5f; v.z *= 0.5f; v.w *= 0.5f;
        ((float4*)sB1q)[tid] = v;
    }

    float wA, wB;
    {
        float cx = Coords[i * 3 + 0], cy = Coords[i * 3 + 1], cz = Coords[i * 3 + 2];
        int jA = j0 + lane, jB = j0 + 32 + lane;
        float dxA = cx - Coords[jA * 3 + 0], dyA = cy - Coords[jA * 3 + 1], dzA = cz - Coords[jA * 3 + 2];
        float dxB = cx - Coords[jB * 3 + 0], dyB = cy - Coords[jB * 3 + 1], dzB = cz - Coords[jB * 3 + 2];
        float sqA = fmaf(dxA, dxA, fmaf(dyA, dyA, dzA * dzA));
        float sqB = fmaf(dxB, dxB, fmaf(dyB, dyB, dzB * dzB));
        float dA = sqA > 0.f ? __fsqrt_rn(sqA) : 0.f;
        float dB = sqB > 0.f ? __fsqrt_rn(sqB) : 0.f;
        wA = Edges[i * N_NODES + jA] * dA;
        wB = Edges[i * N_NODES + jB] * dB;
    }
    __syncthreads();

    const u64 wAh = pack2(0.5f * wA, 0.5f * wA);   // w/2 packed
    const u64 wBh = pack2(0.5f * wB, 0.5f * wB);
    const u64 halfp = pack2(0.5f, 0.5f);

    u64 accA[16], accB[16];
#pragma unroll
    for (int p = 0; p < 16; p++) {
        accA[p] = pack2(c_b2[2 * p], c_b2[2 * p + 1]);
        accB[p] = accA[p];
    }

#pragma unroll 8
    for (int hq = 0; hq < 16; hq++) {
        ulonglong2 aq  = sAq[warp][hq];            // broadcast LDS.128
        ulonglong2 b1q = sB1q[hq];                 // broadcast LDS.128
        ulonglong2 bA  = sBq[hq][lane];            // LDS.128 conflict-free
        ulonglong2 bB  = sBq[hq][32 + lane];

        // hx = (w*(A+B) + b1)/2, then packed swish
        u64 hA01 = swish2_from_half(fma2r(wAh, add2r(aq.x, bA.x), b1q.x));
        u64 hA23 = swish2_from_half(fma2r(wAh, add2r(aq.y, bA.y), b1q.y));
        u64 hB01 = swish2_from_half(fma2r(wBh, add2r(aq.x, bB.x), b1q.x));
        u64 hB23 = swish2_from_half(fma2r(wBh, add2r(aq.y, bB.y), b1q.y));

        float a0, a1, a2, a3, c0, c1, c2, c3;
        unpack2(hA01, a0, a1); unpack2(hA23, a2, a3);
        unpack2(hB01, c0, c1); unpack2(hB23, c2, c3);

        u64 pA0 = pack2(a0, a0), pA1 = pack2(a1, a1);
        u64 pA2 = pack2(a2, a2), pA3 = pack2(a3, a3);
        u64 pB0 = pack2(c0, c0), pB1 = pack2(c1, c1);
        u64 pB2 = pack2(c2, c2), pB3 = pack2(c3, c3);

        const ulonglong2* r0 = (const ulonglong2*)(c_W2T + (4 * hq + 0) * OUTF);
        const ulonglong2* r1 = (const ulonglong2*)(c_W2T + (4 * hq + 1) * OUTF);
        const ulonglong2* r2 = (const ulonglong2*)(c_W2T + (4 * hq + 2) * OUTF);
        const ulonglong2* r3 = (const ulonglong2*)(c_W2T + (4 * hq + 3) * OUTF);
#pragma unroll
        for (int q = 0; q < 8; q++) {
            ulonglong2 w0 = r0[q], w1 = r1[q], w2 = r2[q], w3 = r3[q];
            fma2(accA[2 * q],     pA0, w0.x); fma2(accA[2 * q + 1], pA0, w0.y);
            fma2(accA[2 * q],     pA1, w1.x); fma2(accA[2 * q + 1], pA1, w1.y);
            fma2(accA[2 * q],     pA2, w2.x); fma2(accA[2 * q + 1], pA2, w2.y);
            fma2(accA[2 * q],     pA3, w3.x); fma2(accA[2 * q + 1], pA3, w3.y);
            fma2(accB[2 * q],     pB0, w0.x); fma2(accB[2 * q + 1], pB0, w0.y);
            fma2(accB[2 * q],     pB1, w1.x); fma2(accB[2 * q + 1], pB1, w1.y);
            fma2(accB[2 * q],     pB2, w2.x); fma2(accB[2 * q + 1], pB2, w2.y);
            fma2(accB[2 * q],     pB3, w3.x); fma2(accB[2 * q + 1], pB3, w3.y);
        }
    }

    // ---- epilogue: packed swish + STS.128 stage + LDS.64/STG.64 transpose ----
    float* srow = sOutBase + (warp * 32 + lane) * 36;
    const int o2   = (lane & 15) * 2;
    const int joff = lane >> 4;
#pragma unroll
    for (int s = 0; s < 2; s++) {
        u64* acc = s ? accB : accA;
        float* obase = out + ((size_t)i * N_NODES + j0 + (s ? 32 : 0)) * OUTF;

#pragma unroll
        for (int p = 0; p < 8; p++) {
            u64 v01 = swish2_from_half(mul2r(acc[2 * p],     halfp));
            u64 v23 = swish2_from_half(mul2r(acc[2 * p + 1], halfp));
            float v0, v1, v2, v3;
            unpack2(v01, v0, v1);
            unpack2(v23, v2, v3);
            ((float4*)srow)[p] = make_float4(v0, v1, v2, v3);
        }
        __syncwarp();

        const float* swarp = sOutBase + warp * 32 * 36;
#pragma unroll
        for (int r = 0; r < 16; r++) {
            int jj = 2 * r + joff;
            float2 v = *(const float2*)(swarp + jj * 36 + o2);
            __stcs((float2*)(obase + jj * OUTF + o2), v);
        }
        __syncwarp();
    }
}

// ---------------------------------------------------------------------------
extern "C" void kernel_launch(void* const* d_in, const int* in_sizes, int n_in,
                              void* d_out, int out_size) {
    const float* Edges  = (const float*)d_in[0];
    const float* Coords = (const float*)d_in[1];
    const float* Emb    = (const float*)d_in[2];
    const float* W1     = (const float*)d_in[3];
    const float* b1     = (const float*)d_in[4];
    const float* W2     = (const float*)d_in[5];
    const float* b2     = (const float*)d_in[6];
    float* out = (float*)d_out;

    static bool attr_set = false;
    if (!attr_set) {
        cudaFuncSetAttribute(phi_e_kernel,
                             cudaFuncAttributeMaxDynamicSharedMemorySize,
                             SMEM_TOTAL);
        attr_set = true;
    }

    cudaMemcpyToSymbolAsync(c_b2, b2, OUTF * sizeof(float), 0,
                            cudaMemcpyDeviceToDevice);

    prep_kernel<<<128, 256>>>(Emb, W1, W2);   // also writes g_W2T (block 0)

    void* w2t_dev = nullptr;
    cudaGetSymbolAddress(&w2t_dev, g_W2T);
    cudaMemcpyToSymbolAsync(c_W2T, w2t_dev, HID * OUTF * sizeof(float), 0,
                            cudaMemcpyDeviceToDevice);

    dim3 grid(N_NODES / 64, N_NODES / 8);
    phi_e_kernel<<<grid, 256, SMEM_TOTAL>>>(Edges, Coords, b1, out);
}

// round 14
// speedup vs baseline: 1.5827x; 1.5827x over previous
#include <cuda_runtime.h>
#include <cstdint>

#define N_NODES 1024
#define F_IN    32
#define HID     64
#define OUTF    32

typedef unsigned long long u64;

// Scratch
__device__ float g_A [N_NODES * HID];
__device__ float g_Bq[16 * N_NODES * 4];   // quad-packed: [hq][node][4 floats]
__device__ float g_W2T[HID * OUTF];        // W2^T [h][o]

// Constant copies (uniform broadcast operands -> constant port)
__constant__ float c_W2T[HID * OUTF];
__constant__ float c_b2 [OUTF];

// ---------------------------------------------------------------------------
// Prep: 128 blocks x 256 threads, 8 nodes/block. W1 staged in padded smem.
// Block 0 also writes the W2 transpose into g_W2T.
// ---------------------------------------------------------------------------
__global__ __launch_bounds__(256) void prep_kernel(const float* __restrict__ Emb,
                                                   const float* __restrict__ W1,
                                                   const float* __restrict__ W2) {
    __shared__ float sW1[HID * 65];
    __shared__ float sE[8 * F_IN];
    const int tid = threadIdx.x;
    const int i0  = blockIdx.x * 8;

    if (blockIdx.x == 0) {
        for (int idx = tid; idx < OUTF * HID; idx += 256) {
            int o = idx >> 6, h = idx & 63;
            g_W2T[h * OUTF + o] = W2[idx];
        }
    }

    {
        const float4* w4 = (const float4*)W1;
        for (int v = tid; v < HID * 2 * F_IN / 4; v += 256) {
            float4 w = __ldg(w4 + v);
            int r = v >> 4, c = (v & 15) * 4;
            float* dst = &sW1[r * 65 + c];
            dst[0] = w.x; dst[1] = w.y; dst[2] = w.z; dst[3] = w.w;
        }
    }
    if (tid < 64) {
        float4 e = __ldg((const float4*)(Emb + i0 * F_IN) + tid);
        float* dst = &sE[tid * 4];
        dst[0] = e.x; dst[1] = e.y; dst[2] = e.z; dst[3] = e.w;
    }
    __syncthreads();

    const int h = tid & 63;
    const int g = tid >> 6;
#pragma unroll
    for (int k = 0; k < 2; k++) {
        const int n = g * 2 + k;
        const float* e = &sE[n * F_IN];
        float a = 0.f, b = 0.f;
#pragma unroll
        for (int f = 0; f < F_IN; f++) {
            float ev = e[f];
            a = fmaf(ev, sW1[h * 65 + f], a);
            b = fmaf(ev, sW1[h * 65 + F_IN + f], b);
        }
        const int i = i0 + n;
        g_A[i * HID + h] = a;
        g_Bq[(h >> 2) * (N_NODES * 4) + i * 4 + (h & 3)] = b;
    }
}

// ---------------------------------------------------------------------------
__device__ __forceinline__ u64 pack2(float lo, float hi) {
    u64 r; asm("mov.b64 %0, {%1,%2};" : "=l"(r) : "f"(lo), "f"(hi)); return r;
}
__device__ __forceinline__ void unpack2(u64 v, float& lo, float& hi) {
    asm("mov.b64 {%0,%1}, %2;" : "=f"(lo), "=f"(hi) : "l"(v));
}
__device__ __forceinline__ void fma2(u64& acc, u64 a, u64 b) {
    asm("fma.rn.f32x2 %0, %1, %2, %0;" : "+l"(acc) : "l"(a), "l"(b));
}
__device__ __forceinline__ u64 fma2r(u64 a, u64 b, u64 c) {
    u64 d; asm("fma.rn.f32x2 %0, %1, %2, %3;" : "=l"(d) : "l"(a), "l"(b), "l"(c)); return d;
}
__device__ __forceinline__ u64 add2r(u64 a, u64 b) {
    u64 d; asm("add.rn.f32x2 %0, %1, %2;" : "=l"(d) : "l"(a), "l"(b)); return d;
}
__device__ __forceinline__ u64 mul2r(u64 a, u64 b) {
    u64 d; asm("mul.rn.f32x2 %0, %1, %2;" : "=l"(d) : "l"(a), "l"(b)); return d;
}
__device__ __forceinline__ float tanhf_a(float x) {
    float t; asm("tanh.approx.f32 %0, %1;" : "=f"(t) : "f"(x)); return t;
}
// Packed swish from packed half-inputs: h = hx + hx*tanh(hx), both lanes.
// MUFU tanh is scalar; the multiply-add is packed.
__device__ __forceinline__ u64 swish2_from_half(u64 hx) {
    float x0, x1;
    unpack2(hx, x0, x1);
    u64 tp = pack2(tanhf_a(x0), tanhf_a(x1));
    return fma2r(hx, tp, hx);
}

// ---------------------------------------------------------------------------
// Dynamic smem layout (bytes)
// ---------------------------------------------------------------------------
#define SM_BQ   0        // 16 hq x 64 j x 16B = 16384
#define SM_AQ   16384    // 8 warps x 16 hq x 16B = 2048
#define SM_B1Q  18432    // 16 x 16B = 256 (b1/2, quad-packed)
#define SM_OUT  18688    // 8 warps x 32 lanes x 36 floats = 36864
#define SMEM_TOTAL 55552

// ---------------------------------------------------------------------------
// Main: grid (N/64, N/8), block 256 = 8 warps. Lane owns pairs (i, j0+lane)
// and (i, j0+32+lane). Phase A packed f32x2 (0.5 folded into w and b1, packed
// post-tanh fma); B tile quad-packed for LDS.128; W2^T from constant port;
// b2-preseeded accs; STS.128 + LDS.64/STG.64 transpose epilogue. Unroll 4
// (unroll 8 proven catastrophic in R12).
// ---------------------------------------------------------------------------
__global__ __launch_bounds__(256, 2) void phi_e_kernel(
    const float* __restrict__ Edges,
    const float* __restrict__ Coords,
    const float* __restrict__ b1,
    float* __restrict__ out)
{
    extern __shared__ __align__(16) char smem[];
    ulonglong2 (*sBq)[64] = (ulonglong2(*)[64])(smem + SM_BQ);
    ulonglong2 (*sAq)[16] = (ulonglong2(*)[16])(smem + SM_AQ);
    ulonglong2* sB1q      = (ulonglong2*)(smem + SM_B1Q);
    float*      sOutBase  = (float*)(smem + SM_OUT);

    const int tid  = threadIdx.x;
    const int warp = tid >> 5;
    const int lane = tid & 31;
    const int i0 = blockIdx.y * 8;
    const int j0 = blockIdx.x * 64;
    const int i  = i0 + warp;

    {
        const ulonglong2* src = (const ulonglong2*)g_Bq;
        for (int e = tid; e < 16 * 64; e += 256) {
            int hq = e >> 6, jj = e & 63;
            sBq[hq][jj] = src[hq * N_NODES + j0 + jj];
        }
    }
    if (lane < 16)
        ((float4*)&sAq[warp][0])[lane] = ((const float4*)(g_A + i * HID))[lane];
    if (tid < 16) {
        float4 v = ((const float4*)b1)[tid];
        v.x *= 0.5f; v.y *= 0.5f; v.z *= 0.5f; v.w *= 0.5f;
        ((float4*)sB1q)[tid] = v;
    }

    float wA, wB;
    {
        float cx = Coords[i * 3 + 0], cy = Coords[i * 3 + 1], cz = Coords[i * 3 + 2];
        int jA = j0 + lane, jB = j0 + 32 + lane;
        float dxA = cx - Coords[jA * 3 + 0], dyA = cy - Coords[jA * 3 + 1], dzA = cz - Coords[jA * 3 + 2];
        float dxB = cx - Coords[jB * 3 + 0], dyB = cy - Coords[jB * 3 + 1], dzB = cz - Coords[jB * 3 + 2];
        float sqA = fmaf(dxA, dxA, fmaf(dyA, dyA, dzA * dzA));
        float sqB = fmaf(dxB, dxB, fmaf(dyB, dyB, dzB * dzB));
        float dA = sqA > 0.f ? __fsqrt_rn(sqA) : 0.f;
        float dB = sqB > 0.f ? __fsqrt_rn(sqB) : 0.f;
        wA = Edges[i * N_NODES + jA] * dA;
        wB = Edges[i * N_NODES + jB] * dB;
    }
    __syncthreads();

    const u64 wAh = pack2(0.5f * wA, 0.5f * wA);   // w/2 packed
    const u64 wBh = pack2(0.5f * wB, 0.5f * wB);
    const u64 halfp = pack2(0.5f, 0.5f);

    u64 accA[16], accB[16];
#pragma unroll
    for (int p = 0; p < 16; p++) {
        accA[p] = pack2(c_b2[2 * p], c_b2[2 * p + 1]);
        accB[p] = accA[p];
    }

#pragma unroll 4
    for (int hq = 0; hq < 16; hq++) {
        ulonglong2 aq  = sAq[warp][hq];            // broadcast LDS.128
        ulonglong2 b1q = sB1q[hq];                 // broadcast LDS.128
        ulonglong2 bA  = sBq[hq][lane];            // LDS.128 conflict-free
        ulonglong2 bB  = sBq[hq][32 + lane];

        // hx = (w*(A+B) + b1)/2, then packed swish
        u64 hA01 = swish2_from_half(fma2r(wAh, add2r(aq.x, bA.x), b1q.x));
        u64 hA23 = swish2_from_half(fma2r(wAh, add2r(aq.y, bA.y), b1q.y));
        u64 hB01 = swish2_from_half(fma2r(wBh, add2r(aq.x, bB.x), b1q.x));
        u64 hB23 = swish2_from_half(fma2r(wBh, add2r(aq.y, bB.y), b1q.y));

        float a0, a1, a2, a3, c0, c1, c2, c3;
        unpack2(hA01, a0, a1); unpack2(hA23, a2, a3);
        unpack2(hB01, c0, c1); unpack2(hB23, c2, c3);

        u64 pA0 = pack2(a0, a0), pA1 = pack2(a1, a1);
        u64 pA2 = pack2(a2, a2), pA3 = pack2(a3, a3);
        u64 pB0 = pack2(c0, c0), pB1 = pack2(c1, c1);
        u64 pB2 = pack2(c2, c2), pB3 = pack2(c3, c3);

        const ulonglong2* r0 = (const ulonglong2*)(c_W2T + (4 * hq + 0) * OUTF);
        const ulonglong2* r1 = (const ulonglong2*)(c_W2T + (4 * hq + 1) * OUTF);
        const ulonglong2* r2 = (const ulonglong2*)(c_W2T + (4 * hq + 2) * OUTF);
        const ulonglong2* r3 = (const ulonglong2*)(c_W2T + (4 * hq + 3) * OUTF);
#pragma unroll
        for (int q = 0; q < 8; q++) {
            ulonglong2 w0 = r0[q], w1 = r1[q], w2 = r2[q], w3 = r3[q];
            fma2(accA[2 * q],     pA0, w0.x); fma2(accA[2 * q + 1], pA0, w0.y);
            fma2(accA[2 * q],     pA1, w1.x); fma2(accA[2 * q + 1], pA1, w1.y);
            fma2(accA[2 * q],     pA2, w2.x); fma2(accA[2 * q + 1], pA2, w2.y);
            fma2(accA[2 * q],     pA3, w3.x); fma2(accA[2 * q + 1], pA3, w3.y);
            fma2(accB[2 * q],     pB0, w0.x); fma2(accB[2 * q + 1], pB0, w0.y);
            fma2(accB[2 * q],     pB1, w1.x); fma2(accB[2 * q + 1], pB1, w1.y);
            fma2(accB[2 * q],     pB2, w2.x); fma2(accB[2 * q + 1], pB2, w2.y);
            fma2(accB[2 * q],     pB3, w3.x); fma2(accB[2 * q + 1], pB3, w3.y);
        }
    }

    // ---- epilogue: packed swish + STS.128 stage + LDS.64/STG.64 transpose ----
    float* srow = sOutBase + (warp * 32 + lane) * 36;
    const int o2   = (lane & 15) * 2;
    const int joff = lane >> 4;
#pragma unroll
    for (int s = 0; s < 2; s++) {
        u64* acc = s ? accB : accA;
        float* obase = out + ((size_t)i * N_NODES + j0 + (s ? 32 : 0)) * OUTF;

#pragma unroll
        for (int p = 0; p < 8; p++) {
            u64 v01 = swish2_from_half(mul2r(acc[2 * p],     halfp));
            u64 v23 = swish2_from_half(mul2r(acc[2 * p + 1], halfp));
            float v0, v1, v2, v3;
            unpack2(v01, v0, v1);
            unpack2(v23, v2, v3);
            ((float4*)srow)[p] = make_float4(v0, v1, v2, v3);
        }
        __syncwarp();

        const float* swarp = sOutBase + warp * 32 * 36;
#pragma unroll
        for (int r = 0; r < 16; r++) {
            int jj = 2 * r + joff;
            float2 v = *(const float2*)(swarp + jj * 36 + o2);
            __stcs((float2*)(obase + jj * OUTF + o2), v);
        }
        __syncwarp();
    }
}

// ---------------------------------------------------------------------------
extern "C" void kernel_launch(void* const* d_in, const int* in_sizes, int n_in,
                              void* d_out, int out_size) {
    const float* Edges  = (const float*)d_in[0];
    const float* Coords = (const float*)d_in[1];
    const float* Emb    = (const float*)d_in[2];
    const float* W1     = (const float*)d_in[3];
    const float* b1     = (const float*)d_in[4];
    const float* W2     = (const float*)d_in[5];
    const float* b2     = (const float*)d_in[6];
    float* out = (float*)d_out;

    static bool attr_set = false;
    if (!attr_set) {
        cudaFuncSetAttribute(phi_e_kernel,
                             cudaFuncAttributeMaxDynamicSharedMemorySize,
                             SMEM_TOTAL);
        attr_set = true;
    }

    cudaMemcpyToSymbolAsync(c_b2, b2, OUTF * sizeof(float), 0,
                            cudaMemcpyDeviceToDevice);

    prep_kernel<<<128, 256>>>(Emb, W1, W2);   // also writes g_W2T (block 0)

    void* w2t_dev = nullptr;
    cudaGetSymbolAddress(&w2t_dev, g_W2T);
    cudaMemcpyToSymbolAsync(c_W2T, w2t_dev, HID * OUTF * sizeof(float), 0,
                            cudaMemcpyDeviceToDevice);

    dim3 grid(N_NODES / 64, N_NODES / 8);
    phi_e_kernel<<<grid, 256, SMEM_TOTAL>>>(Edges, Coords, b1, out);
}

// round 15
// speedup vs baseline: 1.7647x; 1.1150x over previous
#include <cuda_runtime.h>
#include <cstdint>

#define N_NODES 1024
#define F_IN    32
#define HID     64
#define OUTF    32

typedef unsigned long long u64;

// Scratch
__device__ float g_A [N_NODES * HID];
__device__ float g_Bq[16 * N_NODES * 4];       // quad-packed: [hq][node][4 floats]
__device__ float g_W2X[HID * OUTF + HID];      // W2^T [h][o] ++ b1/2 (64 floats)

// Constant copy: W2^T followed by packed b1/2
__constant__ float c_W2X[HID * OUTF + HID];
__constant__ float c_b2 [OUTF];

// ---------------------------------------------------------------------------
// Prep: 128 blocks x 256 threads, 8 nodes/block. W1 staged in padded smem.
// Block 0 also writes the W2 transpose and b1/2 into g_W2X.
// ---------------------------------------------------------------------------
__global__ __launch_bounds__(256) void prep_kernel(const float* __restrict__ Emb,
                                                   const float* __restrict__ W1,
                                                   const float* __restrict__ W2,
                                                   const float* __restrict__ b1) {
    __shared__ float sW1[HID * 65];
    __shared__ float sE[8 * F_IN];
    const int tid = threadIdx.x;
    const int i0  = blockIdx.x * 8;

    if (blockIdx.x == 0) {
        for (int idx = tid; idx < OUTF * HID; idx += 256) {
            int o = idx >> 6, h = idx & 63;
            g_W2X[h * OUTF + o] = W2[idx];
        }
        if (tid < HID) g_W2X[HID * OUTF + tid] = 0.5f * b1[tid];
    }

    {
        const float4* w4 = (const float4*)W1;
        for (int v = tid; v < HID * 2 * F_IN / 4; v += 256) {
            float4 w = __ldg(w4 + v);
            int r = v >> 4, c = (v & 15) * 4;
            float* dst = &sW1[r * 65 + c];
            dst[0] = w.x; dst[1] = w.y; dst[2] = w.z; dst[3] = w.w;
        }
    }
    if (tid < 64) {
        float4 e = __ldg((const float4*)(Emb + i0 * F_IN) + tid);
        float* dst = &sE[tid * 4];
        dst[0] = e.x; dst[1] = e.y; dst[2] = e.z; dst[3] = e.w;
    }
    __syncthreads();

    const int h = tid & 63;
    const int g = tid >> 6;
#pragma unroll
    for (int k = 0; k < 2; k++) {
        const int n = g * 2 + k;
        const float* e = &sE[n * F_IN];
        float a = 0.f, b = 0.f;
#pragma unroll
        for (int f = 0; f < F_IN; f++) {
            float ev = e[f];
            a = fmaf(ev, sW1[h * 65 + f], a);
            b = fmaf(ev, sW1[h * 65 + F_IN + f], b);
        }
        const int i = i0 + n;
        g_A[i * HID + h] = a;
        g_Bq[(h >> 2) * (N_NODES * 4) + i * 4 + (h & 3)] = b;
    }
}

// ---------------------------------------------------------------------------
__device__ __forceinline__ u64 pack2(float lo, float hi) {
    u64 r; asm("mov.b64 %0, {%1,%2};" : "=l"(r) : "f"(lo), "f"(hi)); return r;
}
__device__ __forceinline__ void unpack2(u64 v, float& lo, float& hi) {
    asm("mov.b64 {%0,%1}, %2;" : "=f"(lo), "=f"(hi) : "l"(v));
}
__device__ __forceinline__ void fma2(u64& acc, u64 a, u64 b) {
    asm("fma.rn.f32x2 %0, %1, %2, %0;" : "+l"(acc) : "l"(a), "l"(b));
}
__device__ __forceinline__ u64 fma2r(u64 a, u64 b, u64 c) {
    u64 d; asm("fma.rn.f32x2 %0, %1, %2, %3;" : "=l"(d) : "l"(a), "l"(b), "l"(c)); return d;
}
__device__ __forceinline__ u64 add2r(u64 a, u64 b) {
    u64 d; asm("add.rn.f32x2 %0, %1, %2;" : "=l"(d) : "l"(a), "l"(b)); return d;
}
__device__ __forceinline__ u64 mul2r(u64 a, u64 b) {
    u64 d; asm("mul.rn.f32x2 %0, %1, %2;" : "=l"(d) : "l"(a), "l"(b)); return d;
}
__device__ __forceinline__ float tanhf_a(float x) {
    float t; asm("tanh.approx.f32 %0, %1;" : "=f"(t) : "f"(x)); return t;
}
// h = hx + hx*tanh(hx) where hx = pre1/2 (scalar — independent chains
// dual-issue better than the packed variant; proven R11 vs R13).
__device__ __forceinline__ float swish_from_half(float hx) {
    return fmaf(hx, tanhf_a(hx), hx);
}

// ---------------------------------------------------------------------------
// Dynamic smem layout (bytes)
// ---------------------------------------------------------------------------
#define SM_BQ   0        // 16 hq x 64 j x 16B = 16384
#define SM_AQ   16384    // 8 warps x 16 hq x 16B = 2048
#define SM_OUT  18432    // 8 warps x 32 lanes x 36 floats = 36864
#define SMEM_TOTAL 55296

// ---------------------------------------------------------------------------
// Main (R11 structure): grid (N/64, N/8), block 256 = 8 warps. Lane owns pairs
// (i, j0+lane) and (i, j0+32+lane). Phase A packed f32x2 with 0.5 folded into
// w and b1, scalar post-tanh swish; B tile quad-packed for LDS.128; W2^T and
// b1/2 from constant port; b2-preseeded accs; STS.128 + LDS.64/STG.64
// transpose epilogue. Unroll 4.
// ---------------------------------------------------------------------------
__global__ __launch_bounds__(256, 2) void phi_e_kernel(
    const float* __restrict__ Edges,
    const float* __restrict__ Coords,
    float* __restrict__ out)
{
    extern __shared__ __align__(16) char smem[];
    ulonglong2 (*sBq)[64] = (ulonglong2(*)[64])(smem + SM_BQ);
    ulonglong2 (*sAq)[16] = (ulonglong2(*)[16])(smem + SM_AQ);
    float*      sOutBase  = (float*)(smem + SM_OUT);

    const int tid  = threadIdx.x;
    const int warp = tid >> 5;
    const int lane = tid & 31;
    const int i0 = blockIdx.y * 8;
    const int j0 = blockIdx.x * 64;
    const int i  = i0 + warp;

    {
        const ulonglong2* src = (const ulonglong2*)g_Bq;
        for (int e = tid; e < 16 * 64; e += 256) {
            int hq = e >> 6, jj = e & 63;
            sBq[hq][jj] = src[hq * N_NODES + j0 + jj];
        }
    }
    if (lane < 16)
        ((float4*)&sAq[warp][0])[lane] = ((const float4*)(g_A + i * HID))[lane];

    float wA, wB;
    {
        float cx = Coords[i * 3 + 0], cy = Coords[i * 3 + 1], cz = Coords[i * 3 + 2];
        int jA = j0 + lane, jB = j0 + 32 + lane;
        float dxA = cx - Coords[jA * 3 + 0], dyA = cy - Coords[jA * 3 + 1], dzA = cz - Coords[jA * 3 + 2];
        float dxB = cx - Coords[jB * 3 + 0], dyB = cy - Coords[jB * 3 + 1], dzB = cz - Coords[jB * 3 + 2];
        float sqA = fmaf(dxA, dxA, fmaf(dyA, dyA, dzA * dzA));
        float sqB = fmaf(dxB, dxB, fmaf(dyB, dyB, dzB * dzB));
        float dA = sqA > 0.f ? __fsqrt_rn(sqA) : 0.f;
        float dB = sqB > 0.f ? __fsqrt_rn(sqB) : 0.f;
        wA = Edges[i * N_NODES + jA] * dA;
        wB = Edges[i * N_NODES + jB] * dB;
    }
    __syncthreads();

    const u64 wAh = pack2(0.5f * wA, 0.5f * wA);   // w/2 packed
    const u64 wBh = pack2(0.5f * wB, 0.5f * wB);
    const u64 halfp = pack2(0.5f, 0.5f);

    u64 accA[16], accB[16];
#pragma unroll
    for (int p = 0; p < 16; p++) {
        accA[p] = pack2(c_b2[2 * p], c_b2[2 * p + 1]);
        accB[p] = accA[p];
    }

    const ulonglong2* cb1 = (const ulonglong2*)(c_W2X + HID * OUTF);

#pragma unroll 4
    for (int hq = 0; hq < 16; hq++) {
        ulonglong2 aq  = sAq[warp][hq];            // broadcast LDS.128
        ulonglong2 b1q = cb1[hq];                  // uniform LDC.128 (b1/2 pairs)
        ulonglong2 bA  = sBq[hq][lane];            // LDS.128 conflict-free
        ulonglong2 bB  = sBq[hq][32 + lane];

        // hx = (w*(A+B) + b1)/2 directly (0.5 folded into w and b1)
        u64 xA0 = fma2r(wAh, add2r(aq.x, bA.x), b1q.x);
        u64 xA1 = fma2r(wAh, add2r(aq.y, bA.y), b1q.y);
        u64 xB0 = fma2r(wBh, add2r(aq.x, bB.x), b1q.x);
        u64 xB1 = fma2r(wBh, add2r(aq.y, bB.y), b1q.y);

        float a0, a1, a2, a3, c0, c1, c2, c3;
        unpack2(xA0, a0, a1); unpack2(xA1, a2, a3);
        unpack2(xB0, c0, c1); unpack2(xB1, c2, c3);
        a0 = swish_from_half(a0); a1 = swish_from_half(a1);
        a2 = swish_from_half(a2); a3 = swish_from_half(a3);
        c0 = swish_from_half(c0); c1 = swish_from_half(c1);
        c2 = swish_from_half(c2); c3 = swish_from_half(c3);

        u64 pA0 = pack2(a0, a0), pA1 = pack2(a1, a1);
        u64 pA2 = pack2(a2, a2), pA3 = pack2(a3, a3);
        u64 pB0 = pack2(c0, c0), pB1 = pack2(c1, c1);
        u64 pB2 = pack2(c2, c2), pB3 = pack2(c3, c3);

        const ulonglong2* r0 = (const ulonglong2*)(c_W2X + (4 * hq + 0) * OUTF);
        const ulonglong2* r1 = (const ulonglong2*)(c_W2X + (4 * hq + 1) * OUTF);
        const ulonglong2* r2 = (const ulonglong2*)(c_W2X + (4 * hq + 2) * OUTF);
        const ulonglong2* r3 = (const ulonglong2*)(c_W2X + (4 * hq + 3) * OUTF);
#pragma unroll
        for (int q = 0; q < 8; q++) {
            ulonglong2 w0 = r0[q], w1 = r1[q], w2 = r2[q], w3 = r3[q];
            fma2(accA[2 * q],     pA0, w0.x); fma2(accA[2 * q + 1], pA0, w0.y);
            fma2(accA[2 * q],     pA1, w1.x); fma2(accA[2 * q + 1], pA1, w1.y);
            fma2(accA[2 * q],     pA2, w2.x); fma2(accA[2 * q + 1], pA2, w2.y);
            fma2(accA[2 * q],     pA3, w3.x); fma2(accA[2 * q + 1], pA3, w3.y);
            fma2(accB[2 * q],     pB0, w0.x); fma2(accB[2 * q + 1], pB0, w0.y);
            fma2(accB[2 * q],     pB1, w1.x); fma2(accB[2 * q + 1], pB1, w1.y);
            fma2(accB[2 * q],     pB2, w2.x); fma2(accB[2 * q + 1], pB2, w2.y);
            fma2(accB[2 * q],     pB3, w3.x); fma2(accB[2 * q + 1], pB3, w3.y);
        }
    }

    // ---- epilogue: scalar swish + STS.128 stage + LDS.64/STG.64 transpose ----
    float* srow = sOutBase + (warp * 32 + lane) * 36;
    const int o2   = (lane & 15) * 2;
    const int joff = lane >> 4;
#pragma unroll
    for (int s = 0; s < 2; s++) {
        u64* acc = s ? accB : accA;
        float* obase = out + ((size_t)i * N_NODES + j0 + (s ? 32 : 0)) * OUTF;

#pragma unroll
        for (int p = 0; p < 8; p++) {
            u64 h0 = mul2r(acc[2 * p],     halfp);
            u64 h1 = mul2r(acc[2 * p + 1], halfp);
            float v0, v1, v2, v3;
            unpack2(h0, v0, v1);
            unpack2(h1, v2, v3);
            float4 v = make_float4(swish_from_half(v0), swish_from_half(v1),
                                   swish_from_half(v2), swish_from_half(v3));
            ((float4*)srow)[p] = v;
        }
        __syncwarp();

        const float* swarp = sOutBase + warp * 32 * 36;
#pragma unroll
        for (int r = 0; r < 16; r++) {
            int jj = 2 * r + joff;
            float2 v = *(const float2*)(swarp + jj * 36 + o2);
            __stcs((float2*)(obase + jj * OUTF + o2), v);
        }
        __syncwarp();
    }
}

// ---------------------------------------------------------------------------
extern "C" void kernel_launch(void* const* d_in, const int* in_sizes, int n_in,
                              void* d_out, int out_size) {
    const float* Edges  = (const float*)d_in[0];
    const float* Coords = (const float*)d_in[1];
    const float* Emb    = (const float*)d_in[2];
    const float* W1     = (const float*)d_in[3];
    const float* b1     = (const float*)d_in[4];
    const float* W2     = (const float*)d_in[5];
    const float* b2     = (const float*)d_in[6];
    float* out = (float*)d_out;

    static bool attr_set = false;
    if (!attr_set) {
        cudaFuncSetAttribute(phi_e_kernel,
                             cudaFuncAttributeMaxDynamicSharedMemorySize,
                             SMEM_TOTAL);
        attr_set = true;
    }

    cudaMemcpyToSymbolAsync(c_b2, b2, OUTF * sizeof(float), 0,
                            cudaMemcpyDeviceToDevice);

    prep_kernel<<<128, 256>>>(Emb, W1, W2, b1);   // also writes g_W2X (block 0)

    void* w2x_dev = nullptr;
    cudaGetSymbolAddress(&w2x_dev, g_W2X);
    cudaMemcpyToSymbolAsync(c_W2X, w2x_dev, (HID * OUTF + HID) * sizeof(float), 0,
                            cudaMemcpyDeviceToDevice);

    dim3 grid(N_NODES / 64, N_NODES / 8);
    phi_e_kernel<<<grid, 256, SMEM_TOTAL>>>(Edges, Coords, out);
}